// round 1
// baseline (speedup 1.0000x reference)
#include <cuda_runtime.h>

// Problem constants (fixed by the reference)
#define HEADS   16
#define SEQ     4096
#define DIM     64
#define RDIL    2
#define NSEQ    2048        // SEQ / RDIL  (per-offset dilated length)
#define WHALF   64          // window/2
#define QT      32          // query rows per block
#define CT      160         // column union per tile: QT + 2*WHALF
#define NTILES  (NSEQ / QT) // 64
#define NTHREADS 128

// smem strides (floats), padded to kill bank conflicts
#define QS_STRIDE 68
#define KT_STRIDE 161
#define PS_STRIDE 161

#define SMEM_FLOATS (QT*QS_STRIDE + DIM*KT_STRIDE + CT*DIM + QT*PS_STRIDE)
#define SMEM_BYTES  (SMEM_FLOATS * 4)

__global__ void __launch_bounds__(NTHREADS, 1)
dilated_attn_kernel(const float* __restrict__ q,
                    const float* __restrict__ k,
                    const float* __restrict__ v,
                    float* __restrict__ out)
{
    extern __shared__ float smem[];
    float* Qs = smem;                      // [QT][QS_STRIDE]
    float* Kt = Qs + QT * QS_STRIDE;       // [DIM][KT_STRIDE]  (d-major, transposed)
    float* Vs = Kt + DIM * KT_STRIDE;      // [CT][DIM]
    float* Ps = Vs + CT * DIM;             // [QT][PS_STRIDE]

    const int tile = blockIdx.x;
    const int off  = blockIdx.y;
    const int h    = blockIdx.z;
    const int i0   = tile * QT;            // first query row (dilated index)
    const int c0   = i0 - WHALF;           // first column (dilated index), may be < 0

    const int tid = threadIdx.x;
    const size_t headbase = (size_t)h * SEQ * DIM;

    // ---- Load Q tile: 32 rows x 64 (float4 per thread chunk) ----
    {
        const float* qb = q + headbase;
        for (int idx = tid; idx < QT * (DIM / 4); idx += NTHREADS) {
            int r  = idx >> 4;
            int d4 = (idx & 15) << 2;
            int s  = (i0 + r) * RDIL + off;
            float4 val = *reinterpret_cast<const float4*>(qb + (size_t)s * DIM + d4);
            float* dst = Qs + r * QS_STRIDE + d4;
            dst[0] = val.x; dst[1] = val.y; dst[2] = val.z; dst[3] = val.w;
        }
    }
    // ---- Load K tile transposed: Kt[d][cl], zero-fill out of range ----
    {
        const float* kb = k + headbase;
        for (int idx = tid; idx < CT * (DIM / 4); idx += NTHREADS) {
            int cl = idx >> 4;
            int d4 = (idx & 15) << 2;
            int c  = c0 + cl;
            float4 val = make_float4(0.f, 0.f, 0.f, 0.f);
            if (c >= 0 && c < NSEQ) {
                int s = c * RDIL + off;
                val = *reinterpret_cast<const float4*>(kb + (size_t)s * DIM + d4);
            }
            Kt[(d4 + 0) * KT_STRIDE + cl] = val.x;
            Kt[(d4 + 1) * KT_STRIDE + cl] = val.y;
            Kt[(d4 + 2) * KT_STRIDE + cl] = val.z;
            Kt[(d4 + 3) * KT_STRIDE + cl] = val.w;
        }
    }
    // ---- Load V tile natural layout: Vs[cl][d] ----
    {
        const float* vb = v + headbase;
        for (int idx = tid; idx < CT * (DIM / 4); idx += NTHREADS) {
            int cl = idx >> 4;
            int d4 = (idx & 15) << 2;
            int c  = c0 + cl;
            float4 val = make_float4(0.f, 0.f, 0.f, 0.f);
            if (c >= 0 && c < NSEQ) {
                int s = c * RDIL + off;
                val = *reinterpret_cast<const float4*>(vb + (size_t)s * DIM + d4);
            }
            *reinterpret_cast<float4*>(Vs + cl * DIM + d4) = val;
        }
    }
    __syncthreads();

    const int ty = tid >> 4;   // 0..7  -> row group (4 rows each)
    const int tx = tid & 15;   // 0..15 -> column lane (cols tx + 16*cc)

    // ---- Score phase: S[ri][cl] = q_ri . k_cl   (4 rows x 10 cols / thread) ----
    float acc[4][10];
#pragma unroll
    for (int rr = 0; rr < 4; rr++)
#pragma unroll
        for (int cc = 0; cc < 10; cc++) acc[rr][cc] = 0.f;

#pragma unroll 4
    for (int d = 0; d < DIM; d++) {
        float qv[4];
#pragma unroll
        for (int rr = 0; rr < 4; rr++)
            qv[rr] = Qs[(ty * 4 + rr) * QS_STRIDE + d];
        const float* krow = Kt + d * KT_STRIDE + tx;
#pragma unroll
        for (int cc = 0; cc < 10; cc++) {
            float kv = krow[16 * cc];
#pragma unroll
            for (int rr = 0; rr < 4; rr++)
                acc[rr][cc] = fmaf(qv[rr], kv, acc[rr][cc]);
        }
    }

    // ---- Softmax across each row (16 lanes share a row; xor-shuffle reduce) ----
    const float scale = 0.125f;  // 1/sqrt(64)
#pragma unroll
    for (int rr = 0; rr < 4; rr++) {
        const int ri = ty * 4 + rr;
        float m = -1e30f;
#pragma unroll
        for (int cc = 0; cc < 10; cc++) {
            int cl = tx + 16 * cc;
            int c  = c0 + cl;
            // band: cl in [ri, ri+128]; plus sequence range
            bool valid = (cl >= ri) && (cl <= ri + 2 * WHALF) && (c >= 0) && (c < NSEQ);
            float sc = valid ? acc[rr][cc] * scale : -1e30f;
            acc[rr][cc] = sc;
            m = fmaxf(m, sc);
        }
#pragma unroll
        for (int o = 8; o > 0; o >>= 1)
            m = fmaxf(m, __shfl_xor_sync(0xffffffffu, m, o));
        float sum = 0.f;
#pragma unroll
        for (int cc = 0; cc < 10; cc++) {
            float e = (acc[rr][cc] <= -1e29f) ? 0.f : __expf(acc[rr][cc] - m);
            acc[rr][cc] = e;
            sum += e;
        }
#pragma unroll
        for (int o = 8; o > 0; o >>= 1)
            sum += __shfl_xor_sync(0xffffffffu, sum, o);
        float inv = __frcp_rn(sum);
#pragma unroll
        for (int cc = 0; cc < 10; cc++)
            Ps[ri * PS_STRIDE + tx + 16 * cc] = acc[rr][cc] * inv;
    }
    __syncthreads();

    // ---- PV phase: out[ri][dc] = sum_cl P[ri][cl] * V[cl][dc] (4x4 / thread) ----
    float oacc[4][4];
#pragma unroll
    for (int rr = 0; rr < 4; rr++)
#pragma unroll
        for (int cc = 0; cc < 4; cc++) oacc[rr][cc] = 0.f;

#pragma unroll 4
    for (int j = 0; j < CT; j++) {
        float pv[4];
#pragma unroll
        for (int rr = 0; rr < 4; rr++)
            pv[rr] = Ps[(ty * 4 + rr) * PS_STRIDE + j];
        const float* vrow = Vs + j * DIM + tx;
#pragma unroll
        for (int cc = 0; cc < 4; cc++) {
            float vv = vrow[16 * cc];
#pragma unroll
            for (int rr = 0; rr < 4; rr++)
                oacc[rr][cc] = fmaf(pv[rr], vv, oacc[rr][cc]);
        }
    }

    // ---- Scatter back to strided positions ----
    float* ob = out + headbase;
#pragma unroll
    for (int rr = 0; rr < 4; rr++) {
        int s = (i0 + ty * 4 + rr) * RDIL + off;
        float* orow = ob + (size_t)s * DIM + tx;
#pragma unroll
        for (int cc = 0; cc < 4; cc++)
            orow[16 * cc] = oacc[rr][cc];
    }
}

extern "C" void kernel_launch(void* const* d_in, const int* in_sizes, int n_in,
                              void* d_out, int out_size)
{
    const float* q = (const float*)d_in[0];
    const float* k = (const float*)d_in[1];
    const float* v = (const float*)d_in[2];
    float* out = (float*)d_out;

    // Opt-in to >48KB dynamic smem (idempotent; capture-safe, no allocation)
    cudaFuncSetAttribute(dilated_attn_kernel,
                         cudaFuncAttributeMaxDynamicSharedMemorySize, SMEM_BYTES);

    dim3 grid(NTILES, RDIL, HEADS);
    dilated_attn_kernel<<<grid, NTHREADS, SMEM_BYTES>>>(q, k, v, out);
}

// round 3
// speedup vs baseline: 1.0866x; 1.0866x over previous
#include <cuda_runtime.h>

// Problem constants (fixed by the reference)
#define HEADS   16
#define SEQ     4096
#define DIM     64
#define RDIL    2
#define NSEQ    2048        // SEQ / RDIL
#define WHALF   64          // window/2
#define QT      32          // query rows per block
#define CT      160         // column union per tile: QT + 2*WHALF
#define NTILES  (NSEQ / QT) // 64
#define NTHREADS 128

// smem strides (floats); multiples of 4 for float4 alignment
#define QS_STRIDE 68
#define KS_STRIDE 68
#define PS_STRIDE 164

// Ps is aliased into Ks (K is dead after the score phase): 32*164=5248 <= 160*68=10880
#define SMEM_FLOATS (QT*QS_STRIDE + CT*KS_STRIDE + CT*DIM)
#define SMEM_BYTES  (SMEM_FLOATS * 4)

__global__ void __launch_bounds__(NTHREADS)
dilated_attn_kernel(const float* __restrict__ q,
                    const float* __restrict__ k,
                    const float* __restrict__ v,
                    float* __restrict__ out)
{
    extern __shared__ float smem[];
    float* Qs = smem;                       // [QT][QS_STRIDE]
    float* Ks = Qs + QT * QS_STRIDE;        // [CT][KS_STRIDE]  natural [col][d]
    float* Vs = Ks + CT * KS_STRIDE;        // [CT][DIM]
    float* Ps = Ks;                         // [QT][PS_STRIDE]  (aliased: K dead after scores)

    const int tile = blockIdx.x;
    const int off  = blockIdx.y;
    const int h    = blockIdx.z;
    const int i0   = tile * QT;             // first query row (dilated index)
    const int c0   = i0 - WHALF;            // first column (dilated index), may be < 0

    const int tid = threadIdx.x;
    const size_t headbase = (size_t)h * SEQ * DIM;

    // ---- Load Q tile: 32 rows x 64 floats ----
    {
        const float* qb = q + headbase;
        for (int idx = tid; idx < QT * (DIM / 4); idx += NTHREADS) {
            int r  = idx >> 4;
            int d4 = (idx & 15) << 2;
            int s  = (i0 + r) * RDIL + off;
            float4 val = *reinterpret_cast<const float4*>(qb + (size_t)s * DIM + d4);
            *reinterpret_cast<float4*>(Qs + r * QS_STRIDE + d4) = val;
        }
    }
    // ---- Load K tile natural layout: Ks[cl][d], zero-fill out of range ----
    {
        const float* kb = k + headbase;
        for (int idx = tid; idx < CT * (DIM / 4); idx += NTHREADS) {
            int cl = idx >> 4;
            int d4 = (idx & 15) << 2;
            int c  = c0 + cl;
            float4 val = make_float4(0.f, 0.f, 0.f, 0.f);
            if (c >= 0 && c < NSEQ) {
                int s = c * RDIL + off;
                val = *reinterpret_cast<const float4*>(kb + (size_t)s * DIM + d4);
            }
            *reinterpret_cast<float4*>(Ks + cl * KS_STRIDE + d4) = val;
        }
    }
    // ---- Load V tile: Vs[cl][d] ----
    {
        const float* vb = v + headbase;
        for (int idx = tid; idx < CT * (DIM / 4); idx += NTHREADS) {
            int cl = idx >> 4;
            int d4 = (idx & 15) << 2;
            int c  = c0 + cl;
            float4 val = make_float4(0.f, 0.f, 0.f, 0.f);
            if (c >= 0 && c < NSEQ) {
                int s = c * RDIL + off;
                val = *reinterpret_cast<const float4*>(vb + (size_t)s * DIM + d4);
            }
            *reinterpret_cast<float4*>(Vs + cl * DIM + d4) = val;
        }
    }
    __syncthreads();

    const int ty = tid >> 4;   // 0..7  -> row group (4 rows each)
    const int tx = tid & 15;   // 0..15 -> column lane (cols tx + 16*cc)

    // ---- Score phase: acc[rr][cc] = q_(ty*4+rr) . k_(tx+16cc), float4 over d ----
    float acc[4][10];
#pragma unroll
    for (int rr = 0; rr < 4; rr++)
#pragma unroll
        for (int cc = 0; cc < 10; cc++) acc[rr][cc] = 0.f;

    const float* qbase = Qs + (ty * 4) * QS_STRIDE;
    const float* kbase = Ks + tx * KS_STRIDE;

#pragma unroll 4
    for (int d4 = 0; d4 < DIM; d4 += 4) {
        float4 qv[4];
#pragma unroll
        for (int rr = 0; rr < 4; rr++)
            qv[rr] = *reinterpret_cast<const float4*>(qbase + rr * QS_STRIDE + d4);
#pragma unroll
        for (int cc = 0; cc < 10; cc++) {
            float4 kv = *reinterpret_cast<const float4*>(kbase + (16 * cc) * KS_STRIDE + d4);
#pragma unroll
            for (int rr = 0; rr < 4; rr++) {
                acc[rr][cc] = fmaf(qv[rr].x, kv.x, acc[rr][cc]);
                acc[rr][cc] = fmaf(qv[rr].y, kv.y, acc[rr][cc]);
                acc[rr][cc] = fmaf(qv[rr].z, kv.z, acc[rr][cc]);
                acc[rr][cc] = fmaf(qv[rr].w, kv.w, acc[rr][cc]);
            }
        }
    }

    // All Ks reads complete before Ps (aliased) writes
    __syncthreads();

    // ---- Softmax across each row (16 lanes share a row; xor-shuffle reduce) ----
    const float scale = 0.125f;  // 1/sqrt(64)
#pragma unroll
    for (int rr = 0; rr < 4; rr++) {
        const int ri = ty * 4 + rr;
        float m = -1e30f;
#pragma unroll
        for (int cc = 0; cc < 10; cc++) {
            int cl = tx + 16 * cc;
            int c  = c0 + cl;
            bool valid = (cl >= ri) && (cl <= ri + 2 * WHALF) && (c >= 0) && (c < NSEQ);
            float sc = valid ? acc[rr][cc] * scale : -1e30f;
            acc[rr][cc] = sc;
            m = fmaxf(m, sc);
        }
#pragma unroll
        for (int o = 8; o > 0; o >>= 1)
            m = fmaxf(m, __shfl_xor_sync(0xffffffffu, m, o));
        float sum = 0.f;
#pragma unroll
        for (int cc = 0; cc < 10; cc++) {
            float e = (acc[rr][cc] <= -1e29f) ? 0.f : __expf(acc[rr][cc] - m);
            acc[rr][cc] = e;
            sum += e;
        }
#pragma unroll
        for (int o = 8; o > 0; o >>= 1)
            sum += __shfl_xor_sync(0xffffffffu, sum, o);
        float inv = __frcp_rn(sum);
#pragma unroll
        for (int cc = 0; cc < 10; cc++)
            Ps[ri * PS_STRIDE + tx + 16 * cc] = acc[rr][cc] * inv;
    }
    __syncthreads();

    // ---- PV phase: oacc[rr] (float4) = sum_j P[ri][j] * V[j][4tx..4tx+3] ----
    float4 oacc[4];
#pragma unroll
    for (int rr = 0; rr < 4; rr++) oacc[rr] = make_float4(0.f, 0.f, 0.f, 0.f);

    const float* pbase = Ps + (ty * 4) * PS_STRIDE;
    const float* vbase = Vs + 4 * tx;

#pragma unroll 2
    for (int j = 0; j < CT; j += 4) {
        float4 p4[4];
#pragma unroll
        for (int rr = 0; rr < 4; rr++)
            p4[rr] = *reinterpret_cast<const float4*>(pbase + rr * PS_STRIDE + j);
        float4 v0 = *reinterpret_cast<const float4*>(vbase + (j + 0) * DIM);
        float4 v1 = *reinterpret_cast<const float4*>(vbase + (j + 1) * DIM);
        float4 v2 = *reinterpret_cast<const float4*>(vbase + (j + 2) * DIM);
        float4 v3 = *reinterpret_cast<const float4*>(vbase + (j + 3) * DIM);
#pragma unroll
        for (int rr = 0; rr < 4; rr++) {
            oacc[rr].x = fmaf(p4[rr].x, v0.x, oacc[rr].x);
            oacc[rr].y = fmaf(p4[rr].x, v0.y, oacc[rr].y);
            oacc[rr].z = fmaf(p4[rr].x, v0.z, oacc[rr].z);
            oacc[rr].w = fmaf(p4[rr].x, v0.w, oacc[rr].w);
            oacc[rr].x = fmaf(p4[rr].y, v1.x, oacc[rr].x);
            oacc[rr].y = fmaf(p4[rr].y, v1.y, oacc[rr].y);
            oacc[rr].z = fmaf(p4[rr].y, v1.z, oacc[rr].z);
            oacc[rr].w = fmaf(p4[rr].y, v1.w, oacc[rr].w);
            oacc[rr].x = fmaf(p4[rr].z, v2.x, oacc[rr].x);
            oacc[rr].y = fmaf(p4[rr].z, v2.y, oacc[rr].y);
            oacc[rr].z = fmaf(p4[rr].z, v2.z, oacc[rr].z);
            oacc[rr].w = fmaf(p4[rr].z, v2.w, oacc[rr].w);
            oacc[rr].x = fmaf(p4[rr].w, v3.x, oacc[rr].x);
            oacc[rr].y = fmaf(p4[rr].w, v3.y, oacc[rr].y);
            oacc[rr].z = fmaf(p4[rr].w, v3.z, oacc[rr].z);
            oacc[rr].w = fmaf(p4[rr].w, v3.w, oacc[rr].w);
        }
    }

    // ---- Scatter back to strided positions (STG.128, coalesced) ----
    float* ob = out + headbase;
#pragma unroll
    for (int rr = 0; rr < 4; rr++) {
        int s = (i0 + ty * 4 + rr) * RDIL + off;
        *reinterpret_cast<float4*>(ob + (size_t)s * DIM + 4 * tx) = oacc[rr];
    }
}

extern "C" void kernel_launch(void* const* d_in, const int* in_sizes, int n_in,
                              void* d_out, int out_size)
{
    const float* q = (const float*)d_in[0];
    const float* k = (const float*)d_in[1];
    const float* v = (const float*)d_in[2];
    float* out = (float*)d_out;

    cudaFuncSetAttribute(dilated_attn_kernel,
                         cudaFuncAttributeMaxDynamicSharedMemorySize, SMEM_BYTES);

    dim3 grid(NTILES, RDIL, HEADS);
    dilated_attn_kernel<<<grid, NTHREADS, SMEM_BYTES>>>(q, k, v, out);
}